// round 4
// baseline (speedup 1.0000x reference)
#include <cuda_runtime.h>
#include <cuda_bf16.h>

// Device-global scratch (no allocations allowed).
__device__ float g_M1[100 * 100];       // level-1 partials (100 chunk matrices)
__device__ float g_c1[100 * 10];
__device__ float g_M3[100];             // final composed matrix [out][in]
__device__ float g_c3[10];              // final composed bias
__device__ unsigned g_ctr;              // fold-arrival counter (self-resetting)
__device__ volatile unsigned g_flag;    // fold-complete flag (self-resetting)
__device__ unsigned g_done;             // apply-done counter (self-resetting)

#define TPB 256

// ---------------------------------------------------------------------------
// ONE persistent kernel:
//   CTAs 0..99 : fold 10 layers each (phase A); last arrival tree-reduces the
//                100 partials (phase B) -> g_M3/g_c3, sets g_flag.
//   All CTAs   : spin on g_flag, then grid-stride over apply tiles with
//                smem-staged fully-coalesced global access.
// Affine combine rule (apply (M,c) then layer (Wn,bn)): M' = Wn@M, c' = Wn@c+bn.
// ---------------------------------------------------------------------------
__global__ void __launch_bounds__(TPB, 4) fused_kernel(const float* __restrict__ Ws,
                                                       const float* __restrict__ bs,
                                                       const float* __restrict__ x,
                                                       float* __restrict__ out,
                                                       long long pairs,
                                                       long long rows) {
    __shared__ float SH[11008];   // 44KB: phase B needs 11000; apply uses [0,5376) + M/c at 10880
    const int tid = threadIdx.x;
    const int cta = blockIdx.x;

    // ================= FOLD =================
    if (cta < 100) {
        // ---- Phase A: fold layers [10*cta, 10*cta+10) ----
        float* In  = SH;          // 10 x 100
        float* cIn = SH + 1000;   // 10 x 10
        float* M   = SH + 1100;   // 100
        float* cv  = SH + 1200;   // 10

        const float* mb = Ws + (size_t)cta * 1000;
        const float* cb = bs + (size_t)cta * 100;
        for (int idx = tid; idx < 1000; idx += TPB) In[idx]  = mb[idx];
        for (int idx = tid; idx < 100;  idx += TPB) cIn[idx] = cb[idx];
        __syncthreads();

        if (tid < 100) M[tid]  = In[tid];
        if (tid < 10)  cv[tid] = cIn[tid];
        __syncthreads();

        const int ei = (tid % 100) / 10;
        const int ej = tid % 10;

        #pragma unroll 1
        for (int l = 1; l < 10; ++l) {
            float nm = 0.f, nc = 0.f;
            const float* Wn = &In[l * 100];
            if (tid < 100) {
                #pragma unroll
                for (int k = 0; k < 10; ++k) nm += Wn[ei * 10 + k] * M[k * 10 + ej];
            }
            if (tid < 10) {
                nc = cIn[l * 10 + tid];
                #pragma unroll
                for (int k = 0; k < 10; ++k) nc += Wn[tid * 10 + k] * cv[k];
            }
            __syncthreads();
            if (tid < 100) M[tid]  = nm;
            if (tid < 10)  cv[tid] = nc;
            __syncthreads();
        }

        if (tid < 100) g_M1[cta * 100 + tid] = M[tid];
        if (tid < 10)  g_c1[cta * 10 + tid]  = cv[tid];

        __threadfence();
        __syncthreads();
        __shared__ unsigned is_last;
        if (tid == 0) {
            unsigned old = atomicAdd(&g_ctr, 1u);
            is_last = (old == 99u) ? 1u : 0u;
        }
        __syncthreads();

        if (is_last) {
            __threadfence();
            // ---- Phase B: reduce 100 partials -> 1 ----
            float* SM = SH;           // 100 x 100
            float* SC = SH + 10000;   // 100 x 10
            for (int idx = tid; idx < 10000; idx += TPB) SM[idx] = g_M1[idx];
            for (int idx = tid; idx < 1000;  idx += TPB) SC[idx] = g_c1[idx];
            __syncthreads();

            // Level 2: 10 chains of 10 chunks. 2 groups of 100 threads, each
            // folds 5 chains sequentially (45 lockstep steps).
            const int g  = tid / 100;     // 0..1 active (tid < 200)
            const int e  = tid % 100;
            const int i2 = e / 10, j2 = e % 10;
            const bool act = (tid < 200);

            #pragma unroll 1
            for (int s = 0; s < 45; ++s) {
                const int d = g * 5 + s / 9;
                const int l = s % 9 + 1;
                float nm = 0.f, nc = 0.f;
                if (act) {
                    const float* W = &SM[(d * 10 + l) * 100];
                    const float* A = &SM[d * 1000];        // acc = chunk l=0 of chain d
                    #pragma unroll
                    for (int k = 0; k < 10; ++k) nm += W[i2 * 10 + k] * A[k * 10 + j2];
                    if (e < 10) {
                        nc = SC[(d * 10 + l) * 10 + e];
                        #pragma unroll
                        for (int k = 0; k < 10; ++k) nc += W[e * 10 + k] * SC[d * 100 + k];
                    }
                }
                __syncthreads();
                if (act) {
                    SM[d * 1000 + e] = nm;
                    if (e < 10) SC[d * 100 + e] = nc;
                }
                __syncthreads();
            }

            // Level 3: fold the 10 chain results in order.
            #pragma unroll 1
            for (int d = 1; d < 10; ++d) {
                float nm = 0.f, nc = 0.f;
                const float* W = &SM[d * 1000];
                if (tid < 100) {
                    #pragma unroll
                    for (int k = 0; k < 10; ++k) nm += W[i2 * 10 + k] * SM[k * 10 + j2];
                }
                if (tid < 10) {
                    nc = SC[d * 100 + tid];
                    #pragma unroll
                    for (int k = 0; k < 10; ++k) nc += W[tid * 10 + k] * SC[k];
                }
                __syncthreads();
                if (tid < 100) SM[tid] = nm;
                if (tid < 10)  SC[tid] = nc;
                __syncthreads();
            }

            if (tid < 100) g_M3[tid] = SM[tid];
            if (tid < 10)  g_c3[tid] = SC[tid];
            __syncthreads();
            __threadfence();
            if (tid == 0) {
                g_ctr  = 0;     // all 100 arrivals already counted -> safe reset
                g_flag = 1;     // release
            }
        }
    }

    // ================= WAIT FOR FOLD =================
    if (tid == 0) {
        while (g_flag == 0u) __nanosleep(64);
    }
    __syncthreads();
    __threadfence();   // acquire side

    // Copy composed affine into smem (region untouched by apply tiles).
    float* sm = SH + 10880;
    float* sc = SH + 10980;
    if (tid < 100) sm[tid] = g_M3[tid];
    if (tid < 10)  sc[tid] = g_c3[tid];
    __syncthreads();

    // ================= APPLY =================
    // Tile = 256 pairs = 1280 float4. Smem layout: pair p at float offset p*21
    // (20 data + 1 pad; stride 21 is coprime to 32 -> conflict-free per-pair reads).
    const long long nf4    = pairs * 5;            // total float4s over whole pairs
    const long long ntiles = (pairs + (TPB - 1)) / TPB;

    for (long long tile = cta; tile < ntiles; tile += gridDim.x) {
        const long long base4 = tile * (TPB * 5);
        __syncthreads();   // protect SH reuse vs previous iteration's store stage

        // ---- Load stage: fully coalesced LDG.128 -> padded smem ----
        #pragma unroll
        for (int i = 0; i < 5; ++i) {
            const long long g4 = base4 + i * TPB + tid;
            if (g4 < nf4) {
                const float4 v = ((const float4*)x)[g4];
                const int lf = (i * TPB + tid) * 4;   // local float index (mult of 4)
                const int p  = lf / 20;
                const int k  = lf % 20;               // in {0,4,8,12,16} -> never crosses pair
                float* dst = SH + p * 21 + k;
                dst[0] = v.x; dst[1] = v.y; dst[2] = v.z; dst[3] = v.w;
            }
        }
        __syncthreads();

        // ---- Compute: thread t owns pair t of this tile (in-place) ----
        const long long pg = tile * TPB + tid;
        if (pg < pairs) {
            float* row = SH + tid * 21;
            float h[20];
            #pragma unroll
            for (int k = 0; k < 20; ++k) h[k] = row[k];
            float o[20];
            #pragma unroll
            for (int j = 0; j < 10; ++j) {
                float a = sc[j], b2 = sc[j];
                #pragma unroll
                for (int k = 0; k < 10; ++k) {
                    const float mv = sm[j * 10 + k];
                    a  += h[k]      * mv;
                    b2 += h[10 + k] * mv;
                }
                o[j]      = a;
                o[10 + j] = b2;
            }
            #pragma unroll
            for (int k = 0; k < 20; ++k) row[k] = o[k];
        }
        __syncthreads();

        // ---- Store stage: padded smem -> fully coalesced STG.128 ----
        #pragma unroll
        for (int i = 0; i < 5; ++i) {
            const long long g4 = base4 + i * TPB + tid;
            if (g4 < nf4) {
                const int lf = (i * TPB + tid) * 4;
                const int p  = lf / 20;
                const int k  = lf % 20;
                const float* src = SH + p * 21 + k;
                float4 v;
                v.x = src[0]; v.y = src[1]; v.z = src[2]; v.w = src[3];
                ((float4*)out)[g4] = v;
            }
        }
    }

    // Odd-row tail (rows is even for this problem; kept for safety).
    if ((rows & 1LL) && cta == 0 && tid == 0) {
        const long long r = rows - 1;
        const float* xr = x + r * 10;
        float h[10];
        #pragma unroll
        for (int k = 0; k < 10; ++k) h[k] = xr[k];
        float* orow = out + r * 10;
        #pragma unroll
        for (int j = 0; j < 10; ++j) {
            float a = sc[j];
            #pragma unroll
            for (int k = 0; k < 10; ++k) a += h[k] * sm[j * 10 + k];
            orow[j] = a;
        }
    }

    // ================= RESET (replay-safe) =================
    __syncthreads();
    __threadfence();
    if (tid == 0) {
        const unsigned old = atomicAdd(&g_done, 1u);
        if (old == gridDim.x - 1) {   // every CTA has finished all its work
            g_done = 0;
            g_flag = 0;
        }
    }
}

extern "C" void kernel_launch(void* const* d_in, const int* in_sizes, int n_in,
                              void* d_out, int out_size) {
    // Identify inputs by element count: x=BATCH*10, Ws=1000*100, bs=1000*10.
    const float* x  = nullptr;
    const float* Ws = nullptr;
    const float* bs = nullptr;
    long long x_elems = 0;
    for (int i = 0; i < n_in; ++i) {
        if (in_sizes[i] == 1000 * 100) {
            Ws = (const float*)d_in[i];
        } else if (in_sizes[i] == 1000 * 10) {
            bs = (const float*)d_in[i];
        } else {
            x = (const float*)d_in[i];
            x_elems = in_sizes[i];
        }
    }
    const long long rows  = x_elems / 10;
    const long long pairs = rows >> 1;

    // One persistent wave: 148 SMs x 4 CTAs (44KB smem each). >=100 CTAs needed
    // for the fold phase; non-fold CTAs nanosleep-spin until the flag flips, so
    // there is no deadlock even if residency is lower than expected.
    fused_kernel<<<592, TPB>>>(Ws, bs, x, (float*)d_out, pairs, rows);
}